// round 17
// baseline (speedup 1.0000x reference)
#include <cuda_runtime.h>

// Histogram2d: x[32,16384,64] f32 in [0,1) -> hist[32,128,64] * weights[128,64]
//
// Hist at the occupancy ceiling: 256-thread blocks (2 feature-halves x 4
// row-offsets), 32KB smem -> occ 7 = 56 warps/SM (the max the u8 layout
// allows). NCHUNK=32 -> 1024 uniform blocks, one wave, per-SM critical path
// 7x512 = 3584 rows (vs 3840 at occ 3). Per-thread private u8 histograms,
// bank-aligned: word(w,m,l) = w*1024 + m*32 + l keeps every RMW of lane l
// in bank l -> conflict-free, zero atomics in the mainloop. Dump: dp4a
// reduction + one u16x4-in-u64 REDG per (4-bin group, feature) into a 512KB
// per-batch accumulator (carry-free: block partial <= 512, batch total
// <= 16384 < 2^16). Finalize applies weights and zero-restores the
// accumulator for graph replay.

constexpr int B = 32, S = 16384, F = 64, BINS = 128;
constexpr int NCHUNK = 32;             // 32*512 = 16384, uniform blocks
constexpr int CHUNK = 512;             // iters = 128 (<=255 u8-safe, %8==0)
constexpr int THREADS = 256;           // 8 warps: fh = w&1, soff = w>>1 (0..3)
// smem: 8 warps x 1024 words. word(w, m, l) = w*1024 + m*32 + l  (bank = l)
constexpr int SMEM_BYTES = 8 * 1024 * 4;           // 32768 B -> 7 blocks/SM (56 warps)

// u64 accumulators: word W64 = m*64 + f holds bins (4m..4m+3) of feature f:
// lo32 = bins(4m,4m+1) u16x2, hi32 = bins(4m+2,4m+3) u16x2.
constexpr int P64 = (BINS / 4) * F;                // 2048 u64 per batch
__device__ __align__(16) unsigned long long g_accum[(size_t)B * P64];  // 512 KB, starts 0

__global__ __launch_bounds__(THREADS, 7)
void hist_kernel(const float* __restrict__ x) {
    extern __shared__ unsigned int sh[];
    const int tid = threadIdx.x;
    const int w = tid >> 5, l = tid & 31;

    // zero own histogram: word (w, m, l) -> bank l, conflict-free, private
#pragma unroll
    for (int m = 0; m < 32; m++) sh[(w << 10) + (m << 5) + l] = 0u;

    unsigned char* sb = reinterpret_cast<unsigned char*>(sh);
    const unsigned int tbase = (w << 12) + (l << 2);   // byte base of this lane's hist

    const int fh = w & 1;        // feature half: 0 -> f 0..31, 1 -> f 32..63
    const int soff = w >> 1;     // row offset mod 4
    const int f = fh * 32 + l;
    const int b = blockIdx.y, c = blockIdx.x;

    const int row0 = c * CHUNK;
    constexpr int iters = CHUNK / 4;         // 128 <= 255 -> u8 safe
    const float* base = x + (((size_t)b * S + row0 + soff) * F + f);

    constexpr int U = 8;                     // load-ahead for MLP
#pragma unroll 1
    for (int i = 0; i < iters; i += U) {
        float v[U];
#pragma unroll
        for (int u = 0; u < U; u++)
            v[u] = __ldcs(base + (size_t)(i + u) * (4 * F));
#pragma unroll
        for (int u = 0; u < U; u++) {
            // exact trunc(v*128): RZ-add truncates mantissa; bin bits = [16:23)
            const unsigned int bits = __float_as_uint(__fadd_rz(v[u], 1.0f));
            // byte offset ((bin>>2)<<7) | (bin&3): keeps this lane in bank l
            const unsigned int off = (((bits >> 18) & 31u) << 7) | ((bits >> 16) & 3u);
            sb[tbase + off] = (unsigned char)(sb[tbase + off] + 1);
        }
    }
    __syncthreads();

    // Intra-block reduction over 4 row-offsets (dp4a byte extraction),
    // one u64 REDG per (4-bin group, feature): coalesced, fire-and-forget.
    // Per-bin block partial <= 4*128 = 512; batch total <= 16384 < 2^16.
    // smem loads hit bank fl = lane -> conflict-free.
    unsigned long long* outp = g_accum + (size_t)b * P64;
#pragma unroll
    for (int k = 0; k < 8; k++) {
        const int u = tid + THREADS * k;     // 0..2047
        const int fo = u & 63;
        const int m  = u >> 6;               // -> bins 4m..4m+3
        const int fh2 = fo >> 5, fl = fo & 31;
        unsigned int s0 = 0, s1 = 0, s2 = 0, s3 = 0;
#pragma unroll
        for (int s = 0; s < 4; s++) {
            const unsigned int v = sh[((2 * s + fh2) << 10) + (m << 5) + fl];
            s0 = __dp4a(v, 0x00000001u, s0);
            s1 = __dp4a(v, 0x00000100u, s1);
            s2 = __dp4a(v, 0x00010000u, s2);
            s3 = __dp4a(v, 0x01000000u, s3);
        }
        const unsigned long long val =
            (unsigned long long)(s0 | (s1 << 16)) |
            ((unsigned long long)(s2 | (s3 << 16)) << 32);
        atomicAdd(&outp[m * F + fo], val);   // RED.E.ADD.64, no return
    }
}

__global__ __launch_bounds__(256)
void finalize_kernel(const float* __restrict__ wts, float* __restrict__ out) {
    // One thread per u64 accumulator word: B*2048 = 65536 threads, 256 blocks.
    const int idx = blockIdx.x * 256 + threadIdx.x;
    const int b   = idx >> 11;
    const int W64 = idx & 2047;              // m*64 + fo
    const int m   = W64 >> 6;                // bins 4m..4m+3
    const int fo  = W64 & 63;

    uint2* pa = reinterpret_cast<uint2*>(g_accum) + idx;   // coalesced
    const uint2 v = *pa;
    *pa = make_uint2(0u, 0u);                // restore zero for next replay

    const float* wb = wts + (4 * m) * F + fo;
    float* ob = out + ((size_t)b * BINS + 4 * m) * F + fo;
    ob[0 * F] = (float)(v.x & 0xFFFFu) * wb[0 * F];
    ob[1 * F] = (float)(v.x >> 16)     * wb[1 * F];
    ob[2 * F] = (float)(v.y & 0xFFFFu) * wb[2 * F];
    ob[3 * F] = (float)(v.y >> 16)     * wb[3 * F];
}

extern "C" void kernel_launch(void* const* d_in, const int* in_sizes, int n_in,
                              void* d_out, int out_size) {
    const float* x   = (const float*)d_in[0];
    const float* wts = (const float*)d_in[1];
    float* out = (float*)d_out;

    cudaFuncSetAttribute(hist_kernel, cudaFuncAttributeMaxDynamicSharedMemorySize, SMEM_BYTES);

    dim3 grid(NCHUNK, B);   // 32 x 32 = 1024 blocks, one wave at occ 7 (56 warps/SM)
    hist_kernel<<<grid, THREADS, SMEM_BYTES>>>(x);
    finalize_kernel<<<(B * P64) / 256, 256>>>(wts, out);
}